// round 10
// baseline (speedup 1.0000x reference)
#include <cuda_runtime.h>
#include <cuda_bf16.h>
#include <cuda_fp8.h>
#include <cstdint>

// ============================================================================
// SupCon loss, fused + symmetric + FP8 exp-GEMM.
// se_i from S = Xn Xn^T / T via e4m3 mma.sync m16n8k32 (x scaled by 16; only
// exp weights touched by fp8 noise). pd_i/cf_i exact via label buckets + bf16
// dots in finalize. Upper-triangular 128x128 tiles only (2080); off-diag tile
// feeds row-sums (slot jb) and col-sums (slot bi). Deterministic throughout.
// ============================================================================

#define N_TOT   8192
#define D_DIM   128
#define NBLK    64
#define NTILES  (NBLK * (NBLK + 1) / 2)   /* 2080 */
#define KEXP    14.426950408889634f       /* 10*log2(e) */
#define KEXP256 0.05635527503472513f      /* KEXP / 256 (x scaled by 16) */

__device__ __align__(16) __nv_bfloat16 g_x[N_TOT * D_DIM];   // normalized bf16
__device__ __align__(16) uint8_t g_x8[N_TOT * D_DIM];        // 16*x in e4m3
__device__ float g_seb[NBLK][N_TOT];
__device__ float g_loss[N_TOT];
__device__ int   g_is32;
__device__ int   g_part[32][1024];
__device__ int   g_start[1025];
__device__ int   g_items[N_TOT];

// ---------------------------------------------------------------- helpers
__device__ __forceinline__ uint32_t smem_to_u32(const void* p) {
    uint32_t a;
    asm("{ .reg .u64 t; cvta.to.shared.u64 t, %1; cvt.u32.u64 %0, t; }"
        : "=r"(a) : "l"(p));
    return a;
}
__device__ __forceinline__ void ldsm_x4(uint32_t& r0, uint32_t& r1,
                                        uint32_t& r2, uint32_t& r3,
                                        uint32_t addr) {
    asm volatile("ldmatrix.sync.aligned.m8n8.x4.shared.b16 {%0,%1,%2,%3}, [%4];"
                 : "=r"(r0), "=r"(r1), "=r"(r2), "=r"(r3) : "r"(addr));
}
__device__ __forceinline__ void mma_fp8(float& c0, float& c1, float& c2, float& c3,
                                        uint32_t a0, uint32_t a1, uint32_t a2, uint32_t a3,
                                        uint32_t b0, uint32_t b1) {
    asm volatile(
        "mma.sync.aligned.m16n8k32.row.col.f32.e4m3.e4m3.f32 "
        "{%0,%1,%2,%3}, {%4,%5,%6,%7}, {%8,%9}, {%0,%1,%2,%3};"
        : "+f"(c0), "+f"(c1), "+f"(c2), "+f"(c3)
        : "r"(a0), "r"(a1), "r"(a2), "r"(a3), "r"(b0), "r"(b1));
}
__device__ __forceinline__ int getlab(const long long* L64, int is32, int i) {
    return is32 ? ((const int*)L64)[i] : (int)L64[i];
}
#define CP_ASYNC16(dst, src) \
    asm volatile("cp.async.cg.shared.global [%0], [%1], 16;" \
                 :: "r"(dst), "l"(src) : "memory")
#define CP_COMMIT() asm volatile("cp.async.commit_group;" ::: "memory")
#define CP_WAIT0()  asm volatile("cp.async.wait_group 0;" ::: "memory")

// ---------------------------------------------------------------- kernel 1:
// normalize; emit bf16 (exact path) and e4m3 of 16*x (exp-GEMM path).
__global__ void norm_kernel(const float* __restrict__ emb) {
    int row  = blockIdx.x * 8 + (threadIdx.x >> 5);
    int lane = threadIdx.x & 31;
    const float4* e4 = (const float4*)(emb + (size_t)row * D_DIM);
    float4 v = e4[lane];
    float ss = v.x * v.x + v.y * v.y + v.z * v.z + v.w * v.w;
    #pragma unroll
    for (int m = 16; m; m >>= 1) ss += __shfl_xor_sync(0xffffffffu, ss, m);
    float inv = 1.0f / fmaxf(sqrtf(ss), 1e-12f);
    float n0 = v.x * inv, n1 = v.y * inv, n2 = v.z * inv, n3 = v.w * inv;

    __nv_bfloat162* o = (__nv_bfloat162*)(g_x + (size_t)row * D_DIM);
    o[lane * 2]     = __floats2bfloat162_rn(n0, n1);
    o[lane * 2 + 1] = __floats2bfloat162_rn(n2, n3);

    __nv_fp8x4_e4m3 q(make_float4(n0 * 16.f, n1 * 16.f, n2 * 16.f, n3 * 16.f));
    ((uint32_t*)(g_x8 + (size_t)row * D_DIM))[lane] = *(uint32_t*)&q;
}

// ---------------------------------------------------------------- bucket build
__global__ void hist1(const long long* __restrict__ lab64) {
    __shared__ int cnt[1024];
    __shared__ int s_is32;
    int tid = threadIdx.x, blk = blockIdx.x;
    if (tid == 0) s_is32 = 0;
    #pragma unroll
    for (int j = 0; j < 4; j++) cnt[tid + j * 256] = 0;
    __syncthreads();
    if (tid < 64) {
        unsigned hi = (unsigned)(((unsigned long long)lab64[tid]) >> 32);
        if (hi != 0u) atomicOr(&s_is32, 1);
    }
    __syncthreads();
    int is32 = s_is32;
    if (tid == 0 && blk == 0) g_is32 = is32;
    int lab = getlab(lab64, is32, blk * 256 + tid);
    atomicAdd(&cnt[lab], 1);
    __syncthreads();
    #pragma unroll
    for (int j = 0; j < 4; j++) g_part[blk][tid + j * 256] = cnt[tid + j * 256];
}

__global__ void hist2() {
    __shared__ int wsum[32];
    int tid = threadIdx.x;
    int l = tid & 31, w = tid >> 5;
    int pref[32];
    int run = 0;
    #pragma unroll
    for (int c = 0; c < 32; c++) {
        int t = g_part[c][tid];
        pref[c] = run;
        run += t;
    }
    int x = run;
    #pragma unroll
    for (int o = 1; o < 32; o <<= 1) {
        int v = __shfl_up_sync(0xffffffffu, x, o);
        if (l >= o) x += v;
    }
    if (l == 31) wsum[w] = x;
    __syncthreads();
    if (tid < 32) {
        int y = wsum[tid];
        #pragma unroll
        for (int o = 1; o < 32; o <<= 1) {
            int v = __shfl_up_sync(0xffffffffu, y, o);
            if (tid >= o) y += v;
        }
        wsum[tid] = y;
    }
    __syncthreads();
    int incl = x + (w ? wsum[w - 1] : 0);
    int excl = incl - run;
    g_start[tid] = excl;
    if (tid == 0) g_start[1024] = N_TOT;
    #pragma unroll
    for (int c = 0; c < 32; c++) g_part[c][tid] = pref[c] + excl;
}

// hist3: per-warp label counts (leader writes, race-free) + 2-barrier combine.
__global__ void hist3(const long long* __restrict__ lab64) {
    __shared__ int wcnt[8][1024];
    int tid = threadIdx.x, blk = blockIdx.x;
    int l = tid & 31, w = tid >> 5;
    #pragma unroll
    for (int j = 0; j < 32; j++) ((int*)wcnt)[tid + j * 256] = 0;
    int row = blk * 256 + tid;
    int lab = getlab(lab64, g_is32, row);
    unsigned mask = __match_any_sync(0xffffffffu, lab);
    int rank_w = __popc(mask & ((1u << l) - 1u));
    int cnt_w  = __popc(mask);
    __syncthreads();
    if (rank_w == 0) wcnt[w][lab] = cnt_w;     // one leader per (warp,label)
    __syncthreads();
    int base = 0;
    #pragma unroll
    for (int w2 = 0; w2 < 8; w2++)
        if (w2 < w) base += wcnt[w2][lab];
    g_items[g_part[blk][lab] + base + rank_w] = row;
}

// ---------------------------------------------------------------- kernel 2:
// symmetric FP8 GEMM + exp row/col sums. 2080 CTAs, 256 thr (4x2 warps).
// Tiles: 128 rows x 128B e4m3; 16B chunk c of row r stored at c^(r&7).
// smem: [0,16K) A, [16K,32K) B, [32K,+1K) sRow[2][128], [+1K,+3K) sCol[4][128]
__global__ void __launch_bounds__(256, 2) supcon_gemm() {
    extern __shared__ char smem[];
    uint32_t a_sm = smem_to_u32(smem);
    uint32_t b_sm = a_sm + 16384;
    float* sRow = (float*)(smem + 32768);
    float* sCol = (float*)(smem + 32768 + 1024);

    int u = blockIdx.x, bi = 0;
    while (u >= NBLK - bi) { u -= NBLK - bi; bi++; }
    int jb = bi + u;
    bool diag = (jb == bi);

    int tid = threadIdx.x;
    int w   = tid >> 5;
    int l   = tid & 31;
    int wy  = w >> 1;
    int wx  = w & 1;
    int qp  = l & 3;

    // load A (and B unless diag): 1024 chunks of 16B each
    {
        const char* src = (const char*)g_x8 + (size_t)bi * 16384;
        #pragma unroll
        for (int j = 0; j < 4; j++) {
            int it = tid + j * 256;
            int r = it >> 3, c = it & 7;
            CP_ASYNC16(a_sm + r * 128 + ((c ^ (r & 7)) << 4),
                       src + (size_t)it * 16);
        }
    }
    if (!diag) {
        const char* src = (const char*)g_x8 + (size_t)jb * 16384;
        #pragma unroll
        for (int j = 0; j < 4; j++) {
            int it = tid + j * 256;
            int r = it >> 3, c = it & 7;
            CP_ASYNC16(b_sm + r * 128 + ((c ^ (r & 7)) << 4),
                       src + (size_t)it * 16);
        }
    }
    CP_COMMIT();

    int a_row  = 32 * wy + ((l >> 3) & 1) * 8 + (l & 7);
    int a_csel = (l >> 4) & 1;
    int a_rx   = a_row & 7;
    int b_row  = 64 * wx + ((l >> 4) & 1) * 8 + (l & 7);
    int b_csel = (l >> 3) & 1;
    int b_rx   = b_row & 7;

    uint32_t a_base0 = a_sm + a_row * 128;
    uint32_t b_base0 = (diag ? a_sm : b_sm) + b_row * 128;

    CP_WAIT0();
    __syncthreads();

    float acc[2][8][4];
    #pragma unroll
    for (int m = 0; m < 2; m++)
        #pragma unroll
        for (int n = 0; n < 8; n++)
            #pragma unroll
            for (int e = 0; e < 4; e++) acc[m][n][e] = 0.f;

    #pragma unroll
    for (int k = 0; k < 4; k++) {                  // k32 per mma, K=128
        uint32_t ka = (uint32_t)(((2 * k + a_csel) ^ a_rx) << 4);
        uint32_t kb = (uint32_t)(((2 * k + b_csel) ^ b_rx) << 4);
        uint32_t a0[4], a1[4];
        ldsm_x4(a0[0], a0[1], a0[2], a0[3], a_base0 + ka);
        ldsm_x4(a1[0], a1[1], a1[2], a1[3], a_base0 + 2048 + ka);  // +16 rows
        #pragma unroll
        for (int g = 0; g < 4; g++) {
            uint32_t b0, b1, b2, b3;
            ldsm_x4(b0, b1, b2, b3, b_base0 + g * 2048 + kb);
            mma_fp8(acc[0][2*g][0],   acc[0][2*g][1],   acc[0][2*g][2],   acc[0][2*g][3],
                    a0[0], a0[1], a0[2], a0[3], b0, b1);
            mma_fp8(acc[0][2*g+1][0], acc[0][2*g+1][1], acc[0][2*g+1][2], acc[0][2*g+1][3],
                    a0[0], a0[1], a0[2], a0[3], b2, b3);
            mma_fp8(acc[1][2*g][0],   acc[1][2*g][1],   acc[1][2*g][2],   acc[1][2*g][3],
                    a1[0], a1[1], a1[2], a1[3], b0, b1);
            mma_fp8(acc[1][2*g+1][0], acc[1][2*g+1][1], acc[1][2*g+1][2], acc[1][2*g+1][3],
                    a1[0], a1[1], a1[2], a1[3], b2, b3);
        }
    }

    // ---- epilogue: exp once per element; warp-partial row + col sums ----
    // acc holds 256*d (x scaled by 16): exp(10 d - 10) = 2^(acc*KEXP256 - KEXP)
    float rowse[4] = {0.f, 0.f, 0.f, 0.f};
    float colse[16];
    #pragma unroll
    for (int c = 0; c < 16; c++) colse[c] = 0.f;

    #pragma unroll
    for (int m = 0; m < 2; m++)
        #pragma unroll
        for (int n = 0; n < 8; n++) {
            float ex0 = exp2f(fmaf(acc[m][n][0], KEXP256, -KEXP));
            float ex1 = exp2f(fmaf(acc[m][n][1], KEXP256, -KEXP));
            float ex2 = exp2f(fmaf(acc[m][n][2], KEXP256, -KEXP));
            float ex3 = exp2f(fmaf(acc[m][n][3], KEXP256, -KEXP));
            rowse[2*m]     += ex0 + ex1;
            rowse[2*m + 1] += ex2 + ex3;
            colse[2*n]     += ex0 + ex2;
            colse[2*n + 1] += ex1 + ex3;
        }

    #pragma unroll
    for (int v = 0; v < 4; v++) {
        #pragma unroll
        for (int off = 1; off <= 2; off <<= 1)
            rowse[v] += __shfl_xor_sync(0xffffffffu, rowse[v], off);
    }
    if (qp == 0) {
        int q = l >> 2;
        #pragma unroll
        for (int m = 0; m < 2; m++)
            #pragma unroll
            for (int h = 0; h < 2; h++) {
                int row_l = 32 * wy + 16 * m + 8 * h + q;
                sRow[wx * 128 + row_l] = rowse[2*m + h];
            }
    }
    #pragma unroll
    for (int c = 0; c < 16; c++) {
        #pragma unroll
        for (int off = 4; off <= 16; off <<= 1)
            colse[c] += __shfl_xor_sync(0xffffffffu, colse[c], off);
    }
    if (l < 4) {
        #pragma unroll
        for (int n = 0; n < 8; n++)
            #pragma unroll
            for (int e = 0; e < 2; e++) {
                int col_l = 64 * wx + 16 * (n >> 1) + 8 * (n & 1) + l * 2 + e;
                sCol[wy * 128 + col_l] = colse[2*n + e];
            }
    }
    __syncthreads();

    if (tid < 128) {
        g_seb[jb][bi * 128 + tid] = sRow[tid] + sRow[128 + tid];
    } else if (!diag) {
        int c = tid - 128;
        g_seb[bi][jb * 128 + c] = (sCol[c] + sCol[128 + c])
                                + (sCol[256 + c] + sCol[384 + c]);
    }
}

// ---------------------------------------------------------------- kernel 3:
// warp per row: se assemble, diag removal (fp8-consistent), sparse pd/cf.
__global__ void finalize_rows(const long long* __restrict__ lab64) {
    int i = (blockIdx.x * blockDim.x + threadIdx.x) >> 5;
    int l = threadIdx.x & 31;

    // fp8 self-dot (matches what the GEMM put on the diagonal)
    uint32_t xw8 = ((const uint32_t*)(g_x8 + (size_t)i * D_DIM))[l];
    __nv_fp8x4_e4m3 q8 = *(__nv_fp8x4_e4m3*)&xw8;
    float4 xq = (float4)q8;
    float dii8 = xq.x * xq.x + xq.y * xq.y + xq.z * xq.z + xq.w * xq.w;
    #pragma unroll
    for (int m = 16; m; m >>= 1) dii8 += __shfl_xor_sync(0xffffffffu, dii8, m);

    float se = g_seb[l][i] + g_seb[l + 32][i];
    #pragma unroll
    for (int m = 16; m; m >>= 1) se += __shfl_xor_sync(0xffffffffu, se, m);
    se -= exp2f(fmaf(dii8, KEXP256, -KEXP));       // exact cancel of diag term

    // exact bf16 positives
    const uint2* xr = (const uint2*)(g_x + (size_t)i * D_DIM);
    uint2 xv = xr[l];
    __nv_bfloat162 p0 = *(__nv_bfloat162*)&xv.x;
    __nv_bfloat162 p1 = *(__nv_bfloat162*)&xv.y;
    float x0 = __bfloat162float(p0.x), x1 = __bfloat162float(p0.y);
    float x2 = __bfloat162float(p1.x), x3 = __bfloat162float(p1.y);

    int lab = getlab(lab64, g_is32, i);
    int s = g_start[lab], e = g_start[lab + 1];
    float pd = 0.f;
    for (int m = s; m < e; m++) {
        int j = g_items[m];
        if (j == i) continue;
        uint2 yv = ((const uint2*)(g_x + (size_t)j * D_DIM))[l];
        __nv_bfloat162 q0 = *(__nv_bfloat162*)&yv.x;
        __nv_bfloat162 q1 = *(__nv_bfloat162*)&yv.y;
        float d = x0 * __bfloat162float(q0.x) + x1 * __bfloat162float(q0.y)
                + x2 * __bfloat162float(q1.x) + x3 * __bfloat162float(q1.y);
        #pragma unroll
        for (int m2 = 16; m2; m2 >>= 1) d += __shfl_xor_sync(0xffffffffu, d, m2);
        pd += d;
    }
    if (l == 0) {
        float cf  = (float)(e - s - 1);
        float lse = 10.0f + logf(se);
        g_loss[i] = -(10.0f * pd - cf * lse) / (cf + 1.17549435e-38f);
    }
}

// ---------------------------------------------------------------- kernel 4
__global__ void reduce_kernel(float* out) {
    __shared__ float sh[256];
    float a = 0.f;
    for (int k = threadIdx.x; k < N_TOT; k += 256) a += g_loss[k];
    sh[threadIdx.x] = a;
    __syncthreads();
    #pragma unroll
    for (int s = 128; s; s >>= 1) {
        if (threadIdx.x < s) sh[threadIdx.x] += sh[threadIdx.x + s];
        __syncthreads();
    }
    if (threadIdx.x == 0) out[0] = sh[0];
}

// ---------------------------------------------------------------- launch
extern "C" void kernel_launch(void* const* d_in, const int* in_sizes, int n_in,
                              void* d_out, int out_size) {
    const float*     emb    = (const float*)d_in[0];
    const long long* labels = (const long long*)d_in[1];

    cudaFuncSetAttribute(supcon_gemm, cudaFuncAttributeMaxDynamicSharedMemorySize, 36864);

    norm_kernel<<<N_TOT / 8, 256>>>(emb);
    hist1<<<32, 256>>>(labels);
    hist2<<<1, 1024>>>();
    hist3<<<32, 256>>>(labels);
    supcon_gemm<<<NTILES, 256, 36864>>>();
    finalize_rows<<<N_TOT / 8, 256>>>(labels);
    reduce_kernel<<<1, 256>>>((float*)d_out);
}

// round 11
// speedup vs baseline: 1.0982x; 1.0982x over previous
#include <cuda_runtime.h>
#include <cuda_bf16.h>
#include <cstdint>

// ============================================================================
// SupCon loss, fused + symmetric (bf16 mma — fp8 regressed: fallback mma.sync
// is MAC-throughput-bound). Upper-triangular 128x128 tiles (2080): off-diag
// tile (bi,jb) feeds exp row-sums (slot jb) and exp col-sums (slot bi).
// Positives exact via label buckets. Label-bucket chain runs on a FORKED
// stream so the graph overlaps it with norm+gemm. Deterministic throughout.
// ============================================================================

#define N_TOT   8192
#define D_DIM   128
#define NBLK    64
#define NTILES  (NBLK * (NBLK + 1) / 2)   /* 2080 */
#define KEXP    14.426950408889634f       /* 10*log2(e) */

__device__ __align__(16) __nv_bfloat16 g_x[N_TOT * D_DIM];
__device__ float g_seb[NBLK][N_TOT];
__device__ float g_loss[N_TOT];
__device__ int   g_is32;
__device__ int   g_part[32][1024];
__device__ int   g_start[1025];
__device__ int   g_items[N_TOT];

// ---------------------------------------------------------------- helpers
__device__ __forceinline__ uint32_t smem_to_u32(const void* p) {
    uint32_t a;
    asm("{ .reg .u64 t; cvta.to.shared.u64 t, %1; cvt.u32.u64 %0, t; }"
        : "=r"(a) : "l"(p));
    return a;
}
__device__ __forceinline__ void ldsm_x4(uint32_t& r0, uint32_t& r1,
                                        uint32_t& r2, uint32_t& r3,
                                        uint32_t addr) {
    asm volatile("ldmatrix.sync.aligned.m8n8.x4.shared.b16 {%0,%1,%2,%3}, [%4];"
                 : "=r"(r0), "=r"(r1), "=r"(r2), "=r"(r3) : "r"(addr));
}
__device__ __forceinline__ void mma_16816(float& c0, float& c1, float& c2, float& c3,
                                          uint32_t a0, uint32_t a1, uint32_t a2, uint32_t a3,
                                          uint32_t b0, uint32_t b1) {
    asm volatile(
        "mma.sync.aligned.m16n8k16.row.col.f32.bf16.bf16.f32 "
        "{%0,%1,%2,%3}, {%4,%5,%6,%7}, {%8,%9}, {%0,%1,%2,%3};"
        : "+f"(c0), "+f"(c1), "+f"(c2), "+f"(c3)
        : "r"(a0), "r"(a1), "r"(a2), "r"(a3), "r"(b0), "r"(b1));
}
__device__ __forceinline__ int getlab(const long long* L64, int is32, int i) {
    return is32 ? ((const int*)L64)[i] : (int)L64[i];
}
#define CP_ASYNC16(dst, src) \
    asm volatile("cp.async.cg.shared.global [%0], [%1], 16;" \
                 :: "r"(dst), "l"(src) : "memory")
#define CP_COMMIT() asm volatile("cp.async.commit_group;" ::: "memory")
#define CP_WAIT0()  asm volatile("cp.async.wait_group 0;" ::: "memory")

// ---------------------------------------------------------------- kernel 1
__global__ void norm_kernel(const float* __restrict__ emb) {
    int row  = blockIdx.x * 8 + (threadIdx.x >> 5);
    int lane = threadIdx.x & 31;
    const float4* e4 = (const float4*)(emb + (size_t)row * D_DIM);
    float4 v = e4[lane];
    float ss = v.x * v.x + v.y * v.y + v.z * v.z + v.w * v.w;
    #pragma unroll
    for (int m = 16; m; m >>= 1) ss += __shfl_xor_sync(0xffffffffu, ss, m);
    float inv = 1.0f / fmaxf(sqrtf(ss), 1e-12f);
    __nv_bfloat162* o = (__nv_bfloat162*)(g_x + (size_t)row * D_DIM);
    o[lane * 2]     = __floats2bfloat162_rn(v.x * inv, v.y * inv);
    o[lane * 2 + 1] = __floats2bfloat162_rn(v.z * inv, v.w * inv);
}

// ---------------------------------------------------------------- bucket build
__global__ void hist1(const long long* __restrict__ lab64) {
    __shared__ int cnt[1024];
    __shared__ int s_is32;
    int tid = threadIdx.x, blk = blockIdx.x;
    if (tid == 0) s_is32 = 0;
    #pragma unroll
    for (int j = 0; j < 4; j++) cnt[tid + j * 256] = 0;
    __syncthreads();
    if (tid < 64) {
        unsigned hi = (unsigned)(((unsigned long long)lab64[tid]) >> 32);
        if (hi != 0u) atomicOr(&s_is32, 1);
    }
    __syncthreads();
    int is32 = s_is32;
    if (tid == 0 && blk == 0) g_is32 = is32;
    int lab = getlab(lab64, is32, blk * 256 + tid);
    atomicAdd(&cnt[lab], 1);
    __syncthreads();
    #pragma unroll
    for (int j = 0; j < 4; j++) g_part[blk][tid + j * 256] = cnt[tid + j * 256];
}

__global__ void hist2() {
    __shared__ int wsum[32];
    int tid = threadIdx.x;
    int l = tid & 31, w = tid >> 5;
    int pref[32];
    int run = 0;
    #pragma unroll
    for (int c = 0; c < 32; c++) {
        int t = g_part[c][tid];
        pref[c] = run;
        run += t;
    }
    int x = run;
    #pragma unroll
    for (int o = 1; o < 32; o <<= 1) {
        int v = __shfl_up_sync(0xffffffffu, x, o);
        if (l >= o) x += v;
    }
    if (l == 31) wsum[w] = x;
    __syncthreads();
    if (tid < 32) {
        int y = wsum[tid];
        #pragma unroll
        for (int o = 1; o < 32; o <<= 1) {
            int v = __shfl_up_sync(0xffffffffu, y, o);
            if (tid >= o) y += v;
        }
        wsum[tid] = y;
    }
    __syncthreads();
    int incl = x + (w ? wsum[w - 1] : 0);
    int excl = incl - run;
    g_start[tid] = excl;
    if (tid == 0) g_start[1024] = N_TOT;
    #pragma unroll
    for (int c = 0; c < 32; c++) g_part[c][tid] = pref[c] + excl;
}

__global__ void hist3(const long long* __restrict__ lab64) {
    __shared__ int wcnt[8][1024];
    int tid = threadIdx.x, blk = blockIdx.x;
    int l = tid & 31, w = tid >> 5;
    #pragma unroll
    for (int j = 0; j < 32; j++) ((int*)wcnt)[tid + j * 256] = 0;
    int row = blk * 256 + tid;
    int lab = getlab(lab64, g_is32, row);
    unsigned mask = __match_any_sync(0xffffffffu, lab);
    int rank_w = __popc(mask & ((1u << l) - 1u));
    int cnt_w  = __popc(mask);
    __syncthreads();
    if (rank_w == 0) wcnt[w][lab] = cnt_w;
    __syncthreads();
    int base = 0;
    #pragma unroll
    for (int w2 = 0; w2 < 8; w2++)
        if (w2 < w) base += wcnt[w2][lab];
    g_items[g_part[blk][lab] + base + rank_w] = row;
}

// ---------------------------------------------------------------- kernel 2:
// symmetric GEMM + exp row/col sums. 2080 CTAs, 256 thr (4x2 warp grid).
__global__ void __launch_bounds__(256, 2) supcon_gemm() {
    extern __shared__ char smem[];
    uint32_t a_sm = smem_to_u32(smem);
    uint32_t b_sm = a_sm + 32768;
    float* sRow = (float*)(smem + 65536);
    float* sCol = (float*)(smem + 65536 + 1024);

    int u = blockIdx.x, bi = 0;
    while (u >= NBLK - bi) { u -= NBLK - bi; bi++; }
    int jb = bi + u;
    bool diag = (jb == bi);

    int tid = threadIdx.x;
    int w   = tid >> 5;
    int l   = tid & 31;
    int wy  = w >> 1;
    int wx  = w & 1;
    int qp  = l & 3;

    {
        const char* src = (const char*)g_x + (size_t)bi * 32768;
        #pragma unroll
        for (int j = 0; j < 8; j++) {
            int it = tid + j * 256;
            int r = it >> 4, c = it & 15;
            CP_ASYNC16(a_sm + r * 256 + ((c ^ (r & 7)) << 4),
                       src + (size_t)it * 16);
        }
    }
    if (!diag) {
        const char* src = (const char*)g_x + (size_t)jb * 32768;
        #pragma unroll
        for (int j = 0; j < 8; j++) {
            int it = tid + j * 256;
            int r = it >> 4, c = it & 15;
            CP_ASYNC16(b_sm + r * 256 + ((c ^ (r & 7)) << 4),
                       src + (size_t)it * 16);
        }
    }
    CP_COMMIT();

    int a_row  = 32 * wy + ((l >> 3) & 1) * 8 + (l & 7);
    int a_csel = (l >> 4) & 1;
    int a_rx   = a_row & 7;
    int b_row  = 64 * wx + ((l >> 4) & 1) * 8 + (l & 7);
    int b_csel = (l >> 3) & 1;
    int b_rx   = b_row & 7;

    uint32_t a_base0 = a_sm + a_row * 256;
    uint32_t b_base0 = (diag ? a_sm : b_sm) + b_row * 256;

    CP_WAIT0();
    __syncthreads();

    float acc[2][8][4];
    #pragma unroll
    for (int m = 0; m < 2; m++)
        #pragma unroll
        for (int n = 0; n < 8; n++)
            #pragma unroll
            for (int e = 0; e < 4; e++) acc[m][n][e] = 0.f;

    #pragma unroll
    for (int k = 0; k < 8; k++) {
        uint32_t ka = (uint32_t)(((2 * k + a_csel) ^ a_rx) << 4);
        uint32_t kb = (uint32_t)(((2 * k + b_csel) ^ b_rx) << 4);
        uint32_t a0[4], a1[4];
        ldsm_x4(a0[0], a0[1], a0[2], a0[3], a_base0 + ka);
        ldsm_x4(a1[0], a1[1], a1[2], a1[3], a_base0 + 4096 + ka);
        #pragma unroll
        for (int g = 0; g < 4; g++) {
            uint32_t b0, b1, b2, b3;
            ldsm_x4(b0, b1, b2, b3, b_base0 + g * 4096 + kb);
            mma_16816(acc[0][2*g][0],   acc[0][2*g][1],   acc[0][2*g][2],   acc[0][2*g][3],
                      a0[0], a0[1], a0[2], a0[3], b0, b1);
            mma_16816(acc[0][2*g+1][0], acc[0][2*g+1][1], acc[0][2*g+1][2], acc[0][2*g+1][3],
                      a0[0], a0[1], a0[2], a0[3], b2, b3);
            mma_16816(acc[1][2*g][0],   acc[1][2*g][1],   acc[1][2*g][2],   acc[1][2*g][3],
                      a1[0], a1[1], a1[2], a1[3], b0, b1);
            mma_16816(acc[1][2*g+1][0], acc[1][2*g+1][1], acc[1][2*g+1][2], acc[1][2*g+1][3],
                      a1[0], a1[1], a1[2], a1[3], b2, b3);
        }
    }

    float rowse[4] = {0.f, 0.f, 0.f, 0.f};
    float colse[16];
    #pragma unroll
    for (int c = 0; c < 16; c++) colse[c] = 0.f;

    #pragma unroll
    for (int m = 0; m < 2; m++)
        #pragma unroll
        for (int n = 0; n < 8; n++) {
            float ex0 = exp2f(fmaf(acc[m][n][0], KEXP, -KEXP));
            float ex1 = exp2f(fmaf(acc[m][n][1], KEXP, -KEXP));
            float ex2 = exp2f(fmaf(acc[m][n][2], KEXP, -KEXP));
            float ex3 = exp2f(fmaf(acc[m][n][3], KEXP, -KEXP));
            rowse[2*m]     += ex0 + ex1;
            rowse[2*m + 1] += ex2 + ex3;
            colse[2*n]     += ex0 + ex2;
            colse[2*n + 1] += ex1 + ex3;
        }

    #pragma unroll
    for (int v = 0; v < 4; v++) {
        #pragma unroll
        for (int off = 1; off <= 2; off <<= 1)
            rowse[v] += __shfl_xor_sync(0xffffffffu, rowse[v], off);
    }
    if (qp == 0) {
        int q = l >> 2;
        #pragma unroll
        for (int m = 0; m < 2; m++)
            #pragma unroll
            for (int h = 0; h < 2; h++) {
                int row_l = 32 * wy + 16 * m + 8 * h + q;
                sRow[wx * 128 + row_l] = rowse[2*m + h];
            }
    }
    #pragma unroll
    for (int c = 0; c < 16; c++) {
        #pragma unroll
        for (int off = 4; off <= 16; off <<= 1)
            colse[c] += __shfl_xor_sync(0xffffffffu, colse[c], off);
    }
    if (l < 4) {
        #pragma unroll
        for (int n = 0; n < 8; n++)
            #pragma unroll
            for (int e = 0; e < 2; e++) {
                int col_l = 64 * wx + 16 * (n >> 1) + 8 * (n & 1) + l * 2 + e;
                sCol[wy * 128 + col_l] = colse[2*n + e];
            }
    }
    __syncthreads();

    if (tid < 128) {
        g_seb[jb][bi * 128 + tid] = sRow[tid] + sRow[128 + tid];
    } else if (!diag) {
        int c = tid - 128;
        g_seb[bi][jb * 128 + c] = (sCol[c] + sCol[128 + c])
                                + (sCol[256 + c] + sCol[384 + c]);
    }
}

// ---------------------------------------------------------------- kernel 3
__global__ void finalize_rows(const long long* __restrict__ lab64) {
    int i = (blockIdx.x * blockDim.x + threadIdx.x) >> 5;
    int l = threadIdx.x & 31;

    const uint2* xr = (const uint2*)(g_x + (size_t)i * D_DIM);
    uint2 xv = xr[l];
    __nv_bfloat162 p0 = *(__nv_bfloat162*)&xv.x;
    __nv_bfloat162 p1 = *(__nv_bfloat162*)&xv.y;
    float x0 = __bfloat162float(p0.x), x1 = __bfloat162float(p0.y);
    float x2 = __bfloat162float(p1.x), x3 = __bfloat162float(p1.y);

    float dii = x0 * x0 + x1 * x1 + x2 * x2 + x3 * x3;
    #pragma unroll
    for (int m = 16; m; m >>= 1) dii += __shfl_xor_sync(0xffffffffu, dii, m);

    float se = g_seb[l][i] + g_seb[l + 32][i];
    #pragma unroll
    for (int m = 16; m; m >>= 1) se += __shfl_xor_sync(0xffffffffu, se, m);
    se -= exp2f(fmaf(dii, KEXP, -KEXP));

    int lab = getlab(lab64, g_is32, i);
    int s = g_start[lab], e = g_start[lab + 1];
    float pd = 0.f;
    for (int m = s; m < e; m++) {
        int j = g_items[m];
        if (j == i) continue;
        uint2 yv = ((const uint2*)(g_x + (size_t)j * D_DIM))[l];
        __nv_bfloat162 q0 = *(__nv_bfloat162*)&yv.x;
        __nv_bfloat162 q1 = *(__nv_bfloat162*)&yv.y;
        float d = x0 * __bfloat162float(q0.x) + x1 * __bfloat162float(q0.y)
                + x2 * __bfloat162float(q1.x) + x3 * __bfloat162float(q1.y);
        #pragma unroll
        for (int m2 = 16; m2; m2 >>= 1) d += __shfl_xor_sync(0xffffffffu, d, m2);
        pd += d;
    }
    if (l == 0) {
        float cf  = (float)(e - s - 1);
        float lse = 10.0f + logf(se);
        g_loss[i] = -(10.0f * pd - cf * lse) / (cf + 1.17549435e-38f);
    }
}

// ---------------------------------------------------------------- kernel 4
__global__ void reduce_kernel(float* out) {
    __shared__ float sh[256];
    float a = 0.f;
    for (int k = threadIdx.x; k < N_TOT; k += 256) a += g_loss[k];
    sh[threadIdx.x] = a;
    __syncthreads();
    #pragma unroll
    for (int s = 128; s; s >>= 1) {
        if (threadIdx.x < s) sh[threadIdx.x] += sh[threadIdx.x + s];
        __syncthreads();
    }
    if (threadIdx.x == 0) out[0] = sh[0];
}

// ---------------------------------------------------------------- launch:
// fork the label-bucket chain onto a second stream (event fork/join — graph
// capture turns it into parallel branches, hiding it under norm+gemm).
extern "C" void kernel_launch(void* const* d_in, const int* in_sizes, int n_in,
                              void* d_out, int out_size) {
    const float*     emb    = (const float*)d_in[0];
    const long long* labels = (const long long*)d_in[1];

    static cudaStream_t s2 = nullptr;
    static cudaEvent_t evFork = nullptr, evJoin = nullptr;
    if (s2 == nullptr) {
        cudaStreamCreateWithFlags(&s2, cudaStreamNonBlocking);
        cudaEventCreateWithFlags(&evFork, cudaEventDisableTiming);
        cudaEventCreateWithFlags(&evJoin, cudaEventDisableTiming);
        cudaFuncSetAttribute(supcon_gemm,
                             cudaFuncAttributeMaxDynamicSharedMemorySize, 68608);
    }

    // fork: bucket chain on s2 (depends only on labels)
    cudaEventRecord(evFork, 0);
    cudaStreamWaitEvent(s2, evFork, 0);
    hist1<<<32, 256, 0, s2>>>(labels);
    hist2<<<1, 1024, 0, s2>>>();
    hist3<<<32, 256, 0, s2>>>(labels);
    cudaEventRecord(evJoin, s2);

    // main branch: norm -> gemm
    norm_kernel<<<N_TOT / 8, 256>>>(emb);
    supcon_gemm<<<NTILES, 256, 68608>>>();

    // join, then finalize + reduce
    cudaStreamWaitEvent(0, evJoin, 0);
    finalize_rows<<<N_TOT / 8, 256>>>(labels);
    reduce_kernel<<<1, 256>>>((float*)d_out);
}

// round 12
// speedup vs baseline: 1.1185x; 1.0185x over previous
#include <cuda_runtime.h>
#include <cuda_bf16.h>
#include <cstdint>

// ============================================================================
// SupCon loss, fused + symmetric bf16 mma GEMM (legacy-mma MAC ceiling).
// Upper-triangular 128x128 tiles (2080): tile (bi,jb) feeds exp row-sums
// (slot jb) and exp col-sums (slot bi). Positives exact via label buckets.
// Side stream: hist chain + pd/dii kernel hidden under norm+gemm.
// Critical path: norm -> gemm -> loss -> reduce. Deterministic throughout.
// ============================================================================

#define N_TOT   8192
#define D_DIM   128
#define NBLK    64
#define NTILES  (NBLK * (NBLK + 1) / 2)   /* 2080 */
#define KEXP    14.426950408889634f       /* 10*log2(e) */

__device__ __align__(16) __nv_bfloat16 g_x[N_TOT * D_DIM];
__device__ float g_seb[NBLK][N_TOT];
__device__ float g_loss_part[32];
__device__ float g_pd[N_TOT];
__device__ float g_cf[N_TOT];
__device__ float g_dexp[N_TOT];
__device__ int   g_is32;
__device__ int   g_part[32][1024];
__device__ int   g_start[1025];
__device__ int   g_items[N_TOT];

// ---------------------------------------------------------------- helpers
__device__ __forceinline__ uint32_t smem_to_u32(const void* p) {
    uint32_t a;
    asm("{ .reg .u64 t; cvta.to.shared.u64 t, %1; cvt.u32.u64 %0, t; }"
        : "=r"(a) : "l"(p));
    return a;
}
__device__ __forceinline__ void ldsm_x4(uint32_t& r0, uint32_t& r1,
                                        uint32_t& r2, uint32_t& r3,
                                        uint32_t addr) {
    asm volatile("ldmatrix.sync.aligned.m8n8.x4.shared.b16 {%0,%1,%2,%3}, [%4];"
                 : "=r"(r0), "=r"(r1), "=r"(r2), "=r"(r3) : "r"(addr));
}
__device__ __forceinline__ void mma_16816(float& c0, float& c1, float& c2, float& c3,
                                          uint32_t a0, uint32_t a1, uint32_t a2, uint32_t a3,
                                          uint32_t b0, uint32_t b1) {
    asm volatile(
        "mma.sync.aligned.m16n8k16.row.col.f32.bf16.bf16.f32 "
        "{%0,%1,%2,%3}, {%4,%5,%6,%7}, {%8,%9}, {%0,%1,%2,%3};"
        : "+f"(c0), "+f"(c1), "+f"(c2), "+f"(c3)
        : "r"(a0), "r"(a1), "r"(a2), "r"(a3), "r"(b0), "r"(b1));
}
__device__ __forceinline__ int getlab(const long long* L64, int is32, int i) {
    return is32 ? ((const int*)L64)[i] : (int)L64[i];
}
#define CP_ASYNC16(dst, src) \
    asm volatile("cp.async.cg.shared.global [%0], [%1], 16;" \
                 :: "r"(dst), "l"(src) : "memory")
#define CP_COMMIT() asm volatile("cp.async.commit_group;" ::: "memory")
#define CP_WAIT0()  asm volatile("cp.async.wait_group 0;" ::: "memory")

// ---------------------------------------------------------------- kernel 1:
// normalize, 2 rows per warp (doubled MLP). grid 512 x 256.
__global__ void norm_kernel(const float* __restrict__ emb) {
    int gw   = blockIdx.x * 8 + (threadIdx.x >> 5);
    int lane = threadIdx.x & 31;
    int r0 = gw * 2, r1 = r0 + 1;
    float4 v0 = ((const float4*)(emb + (size_t)r0 * D_DIM))[lane];
    float4 v1 = ((const float4*)(emb + (size_t)r1 * D_DIM))[lane];
    float s0 = v0.x * v0.x + v0.y * v0.y + v0.z * v0.z + v0.w * v0.w;
    float s1 = v1.x * v1.x + v1.y * v1.y + v1.z * v1.z + v1.w * v1.w;
    #pragma unroll
    for (int m = 16; m; m >>= 1) {
        s0 += __shfl_xor_sync(0xffffffffu, s0, m);
        s1 += __shfl_xor_sync(0xffffffffu, s1, m);
    }
    float i0 = 1.0f / fmaxf(sqrtf(s0), 1e-12f);
    float i1 = 1.0f / fmaxf(sqrtf(s1), 1e-12f);
    __nv_bfloat162* o0 = (__nv_bfloat162*)(g_x + (size_t)r0 * D_DIM);
    __nv_bfloat162* o1 = (__nv_bfloat162*)(g_x + (size_t)r1 * D_DIM);
    o0[lane * 2]     = __floats2bfloat162_rn(v0.x * i0, v0.y * i0);
    o0[lane * 2 + 1] = __floats2bfloat162_rn(v0.z * i0, v0.w * i0);
    o1[lane * 2]     = __floats2bfloat162_rn(v1.x * i1, v1.y * i1);
    o1[lane * 2 + 1] = __floats2bfloat162_rn(v1.z * i1, v1.w * i1);
}

// ---------------------------------------------------------------- bucket build
__global__ void hist1(const long long* __restrict__ lab64) {
    __shared__ int cnt[1024];
    __shared__ int s_is32;
    int tid = threadIdx.x, blk = blockIdx.x;
    if (tid == 0) s_is32 = 0;
    #pragma unroll
    for (int j = 0; j < 4; j++) cnt[tid + j * 256] = 0;
    __syncthreads();
    if (tid < 64) {
        unsigned hi = (unsigned)(((unsigned long long)lab64[tid]) >> 32);
        if (hi != 0u) atomicOr(&s_is32, 1);
    }
    __syncthreads();
    int is32 = s_is32;
    if (tid == 0 && blk == 0) g_is32 = is32;
    int lab = getlab(lab64, is32, blk * 256 + tid);
    atomicAdd(&cnt[lab], 1);
    __syncthreads();
    #pragma unroll
    for (int j = 0; j < 4; j++) g_part[blk][tid + j * 256] = cnt[tid + j * 256];
}

__global__ void hist2() {
    __shared__ int wsum[32];
    int tid = threadIdx.x;
    int l = tid & 31, w = tid >> 5;
    int pref[32];
    int run = 0;
    #pragma unroll
    for (int c = 0; c < 32; c++) {
        int t = g_part[c][tid];
        pref[c] = run;
        run += t;
    }
    int x = run;
    #pragma unroll
    for (int o = 1; o < 32; o <<= 1) {
        int v = __shfl_up_sync(0xffffffffu, x, o);
        if (l >= o) x += v;
    }
    if (l == 31) wsum[w] = x;
    __syncthreads();
    if (tid < 32) {
        int y = wsum[tid];
        #pragma unroll
        for (int o = 1; o < 32; o <<= 1) {
            int v = __shfl_up_sync(0xffffffffu, y, o);
            if (tid >= o) y += v;
        }
        wsum[tid] = y;
    }
    __syncthreads();
    int incl = x + (w ? wsum[w - 1] : 0);
    int excl = incl - run;
    g_start[tid] = excl;
    if (tid == 0) g_start[1024] = N_TOT;
    #pragma unroll
    for (int c = 0; c < 32; c++) g_part[c][tid] = pref[c] + excl;
}

__global__ void hist3(const long long* __restrict__ lab64) {
    __shared__ int wcnt[8][1024];
    int tid = threadIdx.x, blk = blockIdx.x;
    int l = tid & 31, w = tid >> 5;
    #pragma unroll
    for (int j = 0; j < 32; j++) ((int*)wcnt)[tid + j * 256] = 0;
    int row = blk * 256 + tid;
    int lab = getlab(lab64, g_is32, row);
    unsigned mask = __match_any_sync(0xffffffffu, lab);
    int rank_w = __popc(mask & ((1u << l) - 1u));
    int cnt_w  = __popc(mask);
    __syncthreads();
    if (rank_w == 0) wcnt[w][lab] = cnt_w;
    __syncthreads();
    int base = 0;
    #pragma unroll
    for (int w2 = 0; w2 < 8; w2++)
        if (w2 < w) base += wcnt[w2][lab];
    g_items[g_part[blk][lab] + base + rank_w] = row;
}

// ---------------------------------------------------------------- pd kernel:
// warp per row; runs on side stream hidden under gemm. Computes exact bf16
// positive-dot sum pd, count cf, and the diag exp term.
__global__ void pd_kernel(const long long* __restrict__ lab64) {
    int i = (blockIdx.x * blockDim.x + threadIdx.x) >> 5;
    int l = threadIdx.x & 31;

    const uint2* xr = (const uint2*)(g_x + (size_t)i * D_DIM);
    uint2 xv = xr[l];
    __nv_bfloat162 p0 = *(__nv_bfloat162*)&xv.x;
    __nv_bfloat162 p1 = *(__nv_bfloat162*)&xv.y;
    float x0 = __bfloat162float(p0.x), x1 = __bfloat162float(p0.y);
    float x2 = __bfloat162float(p1.x), x3 = __bfloat162float(p1.y);

    float dii = x0 * x0 + x1 * x1 + x2 * x2 + x3 * x3;
    #pragma unroll
    for (int m = 16; m; m >>= 1) dii += __shfl_xor_sync(0xffffffffu, dii, m);

    int lab = getlab(lab64, g_is32, i);
    int s = g_start[lab], e = g_start[lab + 1];
    float pd = 0.f;
    for (int m = s; m < e; m++) {
        int j = g_items[m];
        if (j == i) continue;
        uint2 yv = ((const uint2*)(g_x + (size_t)j * D_DIM))[l];
        __nv_bfloat162 q0 = *(__nv_bfloat162*)&yv.x;
        __nv_bfloat162 q1 = *(__nv_bfloat162*)&yv.y;
        float d = x0 * __bfloat162float(q0.x) + x1 * __bfloat162float(q0.y)
                + x2 * __bfloat162float(q1.x) + x3 * __bfloat162float(q1.y);
        #pragma unroll
        for (int m2 = 16; m2; m2 >>= 1) d += __shfl_xor_sync(0xffffffffu, d, m2);
        pd += d;
    }
    if (l == 0) {
        g_pd[i]   = pd;
        g_cf[i]   = (float)(e - s - 1);
        g_dexp[i] = exp2f(fmaf(dii, KEXP, -KEXP));
    }
}

// ---------------------------------------------------------------- kernel 2:
// symmetric GEMM + exp row/col sums. 2080 CTAs, 256 thr (4x2 warp grid).
__global__ void __launch_bounds__(256, 2) supcon_gemm() {
    extern __shared__ char smem[];
    uint32_t a_sm = smem_to_u32(smem);
    uint32_t b_sm = a_sm + 32768;
    float* sRow = (float*)(smem + 65536);
    float* sCol = (float*)(smem + 65536 + 1024);

    int u = blockIdx.x, bi = 0;
    while (u >= NBLK - bi) { u -= NBLK - bi; bi++; }
    int jb = bi + u;
    bool diag = (jb == bi);

    int tid = threadIdx.x;
    int w   = tid >> 5;
    int l   = tid & 31;
    int wy  = w >> 1;
    int wx  = w & 1;
    int qp  = l & 3;

    {
        const char* src = (const char*)g_x + (size_t)bi * 32768;
        #pragma unroll
        for (int j = 0; j < 8; j++) {
            int it = tid + j * 256;
            int r = it >> 4, c = it & 15;
            CP_ASYNC16(a_sm + r * 256 + ((c ^ (r & 7)) << 4),
                       src + (size_t)it * 16);
        }
    }
    if (!diag) {
        const char* src = (const char*)g_x + (size_t)jb * 32768;
        #pragma unroll
        for (int j = 0; j < 8; j++) {
            int it = tid + j * 256;
            int r = it >> 4, c = it & 15;
            CP_ASYNC16(b_sm + r * 256 + ((c ^ (r & 7)) << 4),
                       src + (size_t)it * 16);
        }
    }
    CP_COMMIT();

    int a_row  = 32 * wy + ((l >> 3) & 1) * 8 + (l & 7);
    int a_csel = (l >> 4) & 1;
    int a_rx   = a_row & 7;
    int b_row  = 64 * wx + ((l >> 4) & 1) * 8 + (l & 7);
    int b_csel = (l >> 3) & 1;
    int b_rx   = b_row & 7;

    uint32_t a_base0 = a_sm + a_row * 256;
    uint32_t b_base0 = (diag ? a_sm : b_sm) + b_row * 256;

    CP_WAIT0();
    __syncthreads();

    float acc[2][8][4];
    #pragma unroll
    for (int m = 0; m < 2; m++)
        #pragma unroll
        for (int n = 0; n < 8; n++)
            #pragma unroll
            for (int e = 0; e < 4; e++) acc[m][n][e] = 0.f;

    #pragma unroll
    for (int k = 0; k < 8; k++) {
        uint32_t ka = (uint32_t)(((2 * k + a_csel) ^ a_rx) << 4);
        uint32_t kb = (uint32_t)(((2 * k + b_csel) ^ b_rx) << 4);
        uint32_t a0[4], a1[4];
        ldsm_x4(a0[0], a0[1], a0[2], a0[3], a_base0 + ka);
        ldsm_x4(a1[0], a1[1], a1[2], a1[3], a_base0 + 4096 + ka);
        #pragma unroll
        for (int g = 0; g < 4; g++) {
            uint32_t b0, b1, b2, b3;
            ldsm_x4(b0, b1, b2, b3, b_base0 + g * 4096 + kb);
            mma_16816(acc[0][2*g][0],   acc[0][2*g][1],   acc[0][2*g][2],   acc[0][2*g][3],
                      a0[0], a0[1], a0[2], a0[3], b0, b1);
            mma_16816(acc[0][2*g+1][0], acc[0][2*g+1][1], acc[0][2*g+1][2], acc[0][2*g+1][3],
                      a0[0], a0[1], a0[2], a0[3], b2, b3);
            mma_16816(acc[1][2*g][0],   acc[1][2*g][1],   acc[1][2*g][2],   acc[1][2*g][3],
                      a1[0], a1[1], a1[2], a1[3], b0, b1);
            mma_16816(acc[1][2*g+1][0], acc[1][2*g+1][1], acc[1][2*g+1][2], acc[1][2*g+1][3],
                      a1[0], a1[1], a1[2], a1[3], b2, b3);
        }
    }

    float rowse[4] = {0.f, 0.f, 0.f, 0.f};
    float colse[16];
    #pragma unroll
    for (int c = 0; c < 16; c++) colse[c] = 0.f;

    #pragma unroll
    for (int m = 0; m < 2; m++)
        #pragma unroll
        for (int n = 0; n < 8; n++) {
            float ex0 = exp2f(fmaf(acc[m][n][0], KEXP, -KEXP));
            float ex1 = exp2f(fmaf(acc[m][n][1], KEXP, -KEXP));
            float ex2 = exp2f(fmaf(acc[m][n][2], KEXP, -KEXP));
            float ex3 = exp2f(fmaf(acc[m][n][3], KEXP, -KEXP));
            rowse[2*m]     += ex0 + ex1;
            rowse[2*m + 1] += ex2 + ex3;
            colse[2*n]     += ex0 + ex2;
            colse[2*n + 1] += ex1 + ex3;
        }

    #pragma unroll
    for (int v = 0; v < 4; v++) {
        #pragma unroll
        for (int off = 1; off <= 2; off <<= 1)
            rowse[v] += __shfl_xor_sync(0xffffffffu, rowse[v], off);
    }
    if (qp == 0) {
        int q = l >> 2;
        #pragma unroll
        for (int m = 0; m < 2; m++)
            #pragma unroll
            for (int h = 0; h < 2; h++) {
                int row_l = 32 * wy + 16 * m + 8 * h + q;
                sRow[wx * 128 + row_l] = rowse[2*m + h];
            }
    }
    #pragma unroll
    for (int c = 0; c < 16; c++) {
        #pragma unroll
        for (int off = 4; off <= 16; off <<= 1)
            colse[c] += __shfl_xor_sync(0xffffffffu, colse[c], off);
    }
    if (l < 4) {
        #pragma unroll
        for (int n = 0; n < 8; n++)
            #pragma unroll
            for (int e = 0; e < 2; e++) {
                int col_l = 64 * wx + 16 * (n >> 1) + 8 * (n & 1) + l * 2 + e;
                sCol[wy * 128 + col_l] = colse[2*n + e];
            }
    }
    __syncthreads();

    if (tid < 128) {
        g_seb[jb][bi * 128 + tid] = sRow[tid] + sRow[128 + tid];
    } else if (!diag) {
        int c = tid - 128;
        g_seb[bi][jb * 128 + c] = (sCol[c] + sCol[128 + c])
                                + (sCol[256 + c] + sCol[384 + c]);
    }
}

// ---------------------------------------------------------------- loss:
// thread per row; coalesced 64-slot se assembly; block partial sums.
__global__ void loss_kernel() {
    __shared__ float sh[256];
    int i = blockIdx.x * 256 + threadIdx.x;
    float se = 0.f;
    #pragma unroll 8
    for (int s = 0; s < NBLK; s++) se += g_seb[s][i];
    se -= g_dexp[i];
    float cf = g_cf[i];
    float lse = 10.0f + logf(se);
    float loss = -(10.0f * g_pd[i] - cf * lse) / (cf + 1.17549435e-38f);
    sh[threadIdx.x] = loss;
    __syncthreads();
    #pragma unroll
    for (int s = 128; s; s >>= 1) {
        if (threadIdx.x < s) sh[threadIdx.x] += sh[threadIdx.x + s];
        __syncthreads();
    }
    if (threadIdx.x == 0) g_loss_part[blockIdx.x] = sh[0];
}

__global__ void reduce_kernel(float* out) {
    float a = g_loss_part[threadIdx.x];
    #pragma unroll
    for (int m = 16; m; m >>= 1) a += __shfl_xor_sync(0xffffffffu, a, m);
    if (threadIdx.x == 0) out[0] = a;
}

// ---------------------------------------------------------------- launch:
// s2 branch: hist chain, then (after norm) pd kernel -- all hidden under
// norm+gemm on the main stream. Graph capture makes these parallel branches.
extern "C" void kernel_launch(void* const* d_in, const int* in_sizes, int n_in,
                              void* d_out, int out_size) {
    const float*     emb    = (const float*)d_in[0];
    const long long* labels = (const long long*)d_in[1];

    static cudaStream_t s2 = nullptr;
    static cudaEvent_t evFork = nullptr, evNorm = nullptr, evJoin = nullptr;
    if (s2 == nullptr) {
        cudaStreamCreateWithFlags(&s2, cudaStreamNonBlocking);
        cudaEventCreateWithFlags(&evFork, cudaEventDisableTiming);
        cudaEventCreateWithFlags(&evNorm, cudaEventDisableTiming);
        cudaEventCreateWithFlags(&evJoin, cudaEventDisableTiming);
        cudaFuncSetAttribute(supcon_gemm,
                             cudaFuncAttributeMaxDynamicSharedMemorySize, 68608);
    }

    cudaEventRecord(evFork, 0);
    cudaStreamWaitEvent(s2, evFork, 0);
    hist1<<<32, 256, 0, s2>>>(labels);
    hist2<<<1, 1024, 0, s2>>>();
    hist3<<<32, 256, 0, s2>>>(labels);

    norm_kernel<<<512, 256>>>(emb);
    cudaEventRecord(evNorm, 0);
    cudaStreamWaitEvent(s2, evNorm, 0);
    pd_kernel<<<N_TOT / 8, 256, 0, s2>>>(labels);
    cudaEventRecord(evJoin, s2);

    supcon_gemm<<<NTILES, 256, 68608>>>();

    cudaStreamWaitEvent(0, evJoin, 0);
    loss_kernel<<<32, 256>>>();
    reduce_kernel<<<1, 32>>>((float*)d_out);
}